// round 5
// baseline (speedup 1.0000x reference)
#include <cuda_runtime.h>
#include <math.h>

// Problem constants (fixed by the dataset)
#define NNODES   50000
#define FEAT     144        // C_RAD * SH_DIM
#define CRAD     16
#define SHD      9
#define NRBF     128
#define CUTOFF   5.0f
#define TBL      8192       // radial-table resolution
#define SLOTS    64         // edge-id bucket slots per node (overflow -> fallback)
#define OVF_CAP  8192

// ---------------- device scratch (no allocs allowed) ----------------
__device__ float g_table[(TBL + 1) * CRAD];     // rad(d) lookup (+ sentinel row)
__device__ float g_deg[(size_t)NNODES * FEAT];  // aggregated, PRE-SCALED by 1/sqrt(deg_avg)
__device__ int   g_cnt[NNODES];                 // per-dst edge count
__device__ int   g_eid[(size_t)NNODES * SLOTS]; // bucketed edge ids
__device__ int   g_ovf[OVF_CAP];                // overflow edge ids
__device__ int   g_ovfcnt;

#define INV_SQRT_DEG   0.25335570773f   // 1/sqrt(15.57930850982666)
#define INV_SQRT_NODES 0.23549661171f   // 1/sqrt(18.03065905448718)

__device__ __forceinline__ float silu_f(float x) {
    return x / (1.0f + expf(-x));
}

// f32x2 packed-FMA helpers (sm_103a)
__device__ __forceinline__ unsigned long long pk2(float lo, float hi) {
    unsigned long long r;
    asm("mov.b64 %0, {%1, %2};" : "=l"(r) : "f"(lo), "f"(hi));
    return r;
}
__device__ __forceinline__ void fma2(unsigned long long& d,
                                     unsigned long long a, unsigned long long b) {
    asm("fma.rn.f32x2 %0, %1, %2, %0;" : "+l"(d) : "l"(a), "l"(b));
}
__device__ __forceinline__ void unpk2(unsigned long long v, float& lo, float& hi) {
    asm("mov.b64 {%0, %1}, %2;" : "=f"(lo), "=f"(hi) : "l"(v));
}

// per-edge geometry: rad[16] (table interp) + sh[9]
__device__ __forceinline__ void edge_geom(float vx, float vy, float vz,
                                          float* rad, float* sh) {
    const float len = sqrtf(vx * vx + vy * vy + vz * vz);
    const float inv = 1.0f / fmaxf(len, 1e-12f);
    const float x = vx * inv, y = vy * inv, z = vz * inv;

    const float s3 = 1.7320508075688772f;
    const float s5 = 2.23606797749979f;
    const float s15 = 3.872983346207417f;
    sh[0] = 1.0f;
    sh[1] = s3 * x; sh[2] = s3 * y; sh[3] = s3 * z;
    sh[4] = s15 * x * z;
    sh[5] = s15 * x * y;
    sh[6] = s5 * (y * y - 0.5f * (x * x + z * z));
    sh[7] = s15 * y * z;
    sh[8] = 0.5f * s15 * (z * z - x * x);

    float u = len * ((float)TBL / CUTOFF);
    u = fminf(u, (float)TBL);
    int i0 = min((int)u, TBL - 1);
    float f = u - (float)i0;
    const float4* t0 = reinterpret_cast<const float4*>(g_table + (size_t)i0 * CRAD);
    const float4* t1 = reinterpret_cast<const float4*>(g_table + (size_t)(i0 + 1) * CRAD);
    #pragma unroll
    for (int q = 0; q < 4; q++) {
        float4 a = t0[q], b = t1[q];
        rad[4 * q + 0] = fmaf(f, b.x - a.x, a.x);
        rad[4 * q + 1] = fmaf(f, b.y - a.y, a.y);
        rad[4 * q + 2] = fmaf(f, b.z - a.z, a.z);
        rad[4 * q + 3] = fmaf(f, b.w - a.w, a.w);
    }
}

// ---------------- kernel A: zero counters + output ----------------
__global__ void zero_kernel(float* __restrict__ out, int G) {
    int i = blockIdx.x * blockDim.x + threadIdx.x;
    if (i < NNODES) g_cnt[i] = 0;
    if (i < G) out[i] = 0.0f;
    if (i == 0) g_ovfcnt = 0;
}

// ---------------- kernel B (fat): radial table + edge-id bucketing ----------------
__global__ void __launch_bounds__(256) fat_kernel(const float* __restrict__ W1, const float* __restrict__ b1,
                                                  const float* __restrict__ W2, const float* __restrict__ b2,
                                                  const float* __restrict__ W3,
                                                  const int* __restrict__ edst, int E) {
    if (blockIdx.x < TBL + 1) {
        __shared__ float s_rbf[NRBF];
        __shared__ float s_h1[64];
        __shared__ float s_h2[64];

        const int i = blockIdx.x;
        const int t = threadIdx.x;
        const float d = (float)i * (CUTOFF / (float)TBL);

        const double startd = 0.006737946999085467;          // exp(-5)
        const double width  = (2.0 / 128.0) * (1.0 - startd);
        const float  BETA   = (float)(1.0 / (width * width));

        if (t < NRBF) {
            const float mean = (float)(startd + (1.0 - startd) * ((double)t / 127.0));
            float cut = 0.0f;
            if (d < CUTOFF)
                cut = 0.5f * (cosf(d * (float)(3.14159265358979323846 / 5.0)) + 1.0f);
            const float ex = expf(-d);
            const float dd = ex - mean;
            s_rbf[t] = cut * expf(-BETA * dd * dd);
        }
        __syncthreads();

        if (t < 64) {
            float a = b1[t];
            #pragma unroll 8
            for (int k = 0; k < NRBF; k++) a = fmaf(s_rbf[k], W1[k * 64 + t], a);
            s_h1[t] = silu_f(a);
        }
        __syncthreads();
        if (t < 64) {
            float a = b2[t];
            #pragma unroll 8
            for (int k = 0; k < 64; k++) a = fmaf(s_h1[k], W2[k * 64 + t], a);
            s_h2[t] = silu_f(a);
        }
        __syncthreads();
        if (t < CRAD) {
            float a = 0.0f;
            #pragma unroll 8
            for (int k = 0; k < 64; k++) a = fmaf(s_h2[k], W3[k * CRAD + t], a);
            g_table[i * CRAD + t] = a;
        }
    } else {
        const int e = (blockIdx.x - (TBL + 1)) * 256 + threadIdx.x;
        if (e < E) {
            const int d = edst[e];
            const int pos = atomicAdd(&g_cnt[d], 1);
            if (pos < SLOTS) {
                g_eid[(size_t)d * SLOTS + pos] = e;
            } else {
                const int oi = atomicAdd(&g_ovfcnt, 1);
                if (oi < OVF_CAP) g_ovf[oi] = e;
            }
        }
    }
}

// ---------------- kernel C: warp-per-node gather ----------------
// Lane mapping: lane = 2*c + h; c in [0,16), h in {0,1}. Lane owns outputs
// j = 9*c + k for k in [h?5:0, h?9:5). smem row padded to 29 (gcd(29,32)=1).
__global__ void __launch_bounds__(256) gather_kernel(const float* __restrict__ pos,
                                                     const int* __restrict__ esrc,
                                                     int N) {
    __shared__ float sE[8][32][29];   // [warp][edge][rad16|sh9|pad]

    const int w = threadIdx.x >> 5;           // warp in block
    const int lane = threadIdx.x & 31;
    const int n = blockIdx.x * 8 + w;         // node
    if (n >= N) return;

    const int deg = g_cnt[n];
    const int nslot = min(deg, SLOTS);

    const float pdx = pos[3 * (size_t)n + 0];
    const float pdy = pos[3 * (size_t)n + 1];
    const float pdz = pos[3 * (size_t)n + 2];

    const int c = lane >> 1;
    const int h = lane & 1;
    const int k0 = h ? 5 : 0;
    const int nk = h ? 4 : 5;

    float acc[5] = {0.f, 0.f, 0.f, 0.f, 0.f};

    for (int base = 0; base < nslot; base += 32) {
        const int cnt = min(nslot - base, 32);
        float rad[CRAD], sh[SHD];
        if (lane < cnt) {
            const int e = g_eid[(size_t)n * SLOTS + base + lane];
            const int s = esrc[e];
            const float vx = pos[3 * (size_t)s + 0] - pdx;
            const float vy = pos[3 * (size_t)s + 1] - pdy;
            const float vz = pos[3 * (size_t)s + 2] - pdz;
            edge_geom(vx, vy, vz, rad, sh);
            #pragma unroll
            for (int q = 0; q < CRAD; q++) sE[w][lane][q] = rad[q];
            #pragma unroll
            for (int q = 0; q < SHD; q++) sE[w][lane][CRAD + q] = sh[q];
        }
        __syncwarp();
        for (int e2 = 0; e2 < cnt; e2++) {
            const float r = sE[w][e2][c];
            #pragma unroll
            for (int m = 0; m < 5; m++) {
                if (m < nk) acc[m] = fmaf(r, sE[w][e2][CRAD + k0 + m], acc[m]);
            }
        }
        __syncwarp();
    }

    float* dst = g_deg + (size_t)n * FEAT + 9 * c + k0;
    #pragma unroll
    for (int m = 0; m < 5; m++) {
        if (m < nk) dst[m] = acc[m] * INV_SQRT_DEG;
    }
}

// ---------------- kernel D: node head + graph reduction (+ overflow fixup) ----------------
// Block: 288 threads = 8 node-groups x 36 j-groups (4 j each).
// sNF staged as packed {v,v} f32x2 pairs: inner loop = LDS.64 + 2 fma2.
__global__ void __launch_bounds__(288) node_kernel(const float* __restrict__ atab,
                                                   const int* __restrict__ natom,
                                                   const float* __restrict__ Wh1,
                                                   const float* __restrict__ bh1,
                                                   const float* __restrict__ Wh2,
                                                   const float* __restrict__ bh2,
                                                   const int* __restrict__ batch,
                                                   const float* __restrict__ pos,
                                                   const int* __restrict__ esrc,
                                                   const int* __restrict__ edst,
                                                   float* __restrict__ out,
                                                   int N) {
    __shared__ unsigned long long sNF2[32][FEAT];   // 36,864 B: packed {v,v}
    __shared__ int s_atom[32];

    const int t = threadIdx.x;
    const int tx = t % 36;          // j0 = 4*tx
    const int ty = t / 36;          // 0..7
    const int nb = blockIdx.x * 32;

    if (t < 32) {
        const int gn = nb + t;
        s_atom[t] = (gn < N) ? natom[gn] : 0;
    }
    __syncthreads();

    // stage node features as packed pairs (float2-vectorized: 32*72 float2 elems)
    for (int idx = t; idx < 32 * (FEAT / 2); idx += 288) {
        const int n = idx / (FEAT / 2);
        const int kk = idx - n * (FEAT / 2);
        const int k = 2 * kk;
        const int gn = nb + n;
        float v0 = 0.0f, v1 = 0.0f;
        if (gn < N) {
            const float2 a = *reinterpret_cast<const float2*>(atab + (size_t)s_atom[n] * FEAT + k);
            const float2 g = *reinterpret_cast<const float2*>(g_deg + (size_t)gn * FEAT + k);
            v0 = a.x + g.x;
            v1 = a.y + g.y;
        }
        sNF2[n][k]     = pk2(v0, v0);
        sNF2[n][k + 1] = pk2(v1, v1);
    }
    __syncthreads();

    // overflow fixup (practically never taken; g_ovfcnt == 0 for this graph)
    const int novf = g_ovfcnt;
    if (novf > 0) {
        for (int i = t; i < min(novf, OVF_CAP); i += 288) {
            const int e = g_ovf[i];
            const int d = edst[e];
            if (d >= nb && d < nb + 32 && d < N) {
                const int s = esrc[e];
                const float vx = pos[3 * (size_t)s + 0] - pos[3 * (size_t)d + 0];
                const float vy = pos[3 * (size_t)s + 1] - pos[3 * (size_t)d + 1];
                const float vz = pos[3 * (size_t)s + 2] - pos[3 * (size_t)d + 2];
                float rad[CRAD], sh[SHD];
                edge_geom(vx, vy, vz, rad, sh);
                float* row = reinterpret_cast<float*>(&sNF2[d - nb][0]);
                for (int j = 0; j < FEAT; j++) {
                    const float add = rad[j / SHD] * sh[j % SHD] * INV_SQRT_DEG;
                    atomicAdd(row + 2 * j + 0, add);
                    atomicAdd(row + 2 * j + 1, add);
                }
            }
        }
        __syncthreads();
    }

    unsigned long long acc01[4], acc23[4];
    #pragma unroll
    for (int nn = 0; nn < 4; nn++) { acc01[nn] = 0ULL; acc23[nn] = 0ULL; }

    const int j0 = 4 * tx;
    #pragma unroll 4
    for (int k = 0; k < FEAT; k++) {
        const float4 w = __ldg(reinterpret_cast<const float4*>(Wh1 + (size_t)k * FEAT + j0));
        const unsigned long long w01 = pk2(w.x, w.y);
        const unsigned long long w23 = pk2(w.z, w.w);
        #pragma unroll
        for (int nn = 0; nn < 4; nn++) {
            const unsigned long long vv = sNF2[ty + 8 * nn][k];
            fma2(acc01[nn], vv, w01);
            fma2(acc23[nn], vv, w23);
        }
    }

    const float4 b4 = *reinterpret_cast<const float4*>(bh1 + j0);
    const float4 w2 = *reinterpret_cast<const float4*>(Wh2 + j0);
    const float bias2 = bh2[0];

    #pragma unroll
    for (int nn = 0; nn < 4; nn++) {
        const int gn = nb + ty + 8 * nn;
        if (gn >= N) continue;
        float a0, a1, a2, a3;
        unpk2(acc01[nn], a0, a1);
        unpk2(acc23[nn], a2, a3);
        float p = silu_f(a0 + b4.x) * w2.x
                + silu_f(a1 + b4.y) * w2.y
                + silu_f(a2 + b4.z) * w2.z
                + silu_f(a3 + b4.w) * w2.w;
        if (tx == 0) p += bias2;
        atomicAdd(out + batch[gn], p * INV_SQRT_NODES);
    }
}

// ---------------- launcher ----------------
extern "C" void kernel_launch(void* const* d_in, const int* in_sizes, int n_in,
                              void* d_out, int out_size) {
    const float* pos  = (const float*)d_in[0];
    const float* atab = (const float*)d_in[1];
    const float* W1   = (const float*)d_in[2];
    const float* b1   = (const float*)d_in[3];
    const float* W2   = (const float*)d_in[4];
    const float* b2   = (const float*)d_in[5];
    const float* W3   = (const float*)d_in[6];
    const float* Wh1  = (const float*)d_in[7];
    const float* bh1  = (const float*)d_in[8];
    const float* Wh2  = (const float*)d_in[9];
    const float* bh2  = (const float*)d_in[10];
    const int* natom  = (const int*)d_in[11];
    const int* esrc   = (const int*)d_in[12];
    const int* edst   = (const int*)d_in[13];
    const int* batch  = (const int*)d_in[14];
    float* out = (float*)d_out;

    const int N = in_sizes[11];
    const int E = in_sizes[12];
    const int G = out_size;

    // 1: zero counters + output
    zero_kernel<<<(NNODES + 255) / 256, 256>>>(out, G);

    // 2: radial table + edge bucketing (independent halves, one launch)
    const int scatter_blocks = (E + 255) / 256;
    fat_kernel<<<(TBL + 1) + scatter_blocks, 256>>>(W1, b1, W2, b2, W3, edst, E);

    // 3: warp-per-node gather (writes g_deg fully; no zeroing needed)
    gather_kernel<<<(N + 7) / 8, 256>>>(pos, esrc, N);

    // 4: node head + graph reduction (+ inline overflow fixup) — profiled launch
    node_kernel<<<(N + 31) / 32, 288>>>(atab, natom, Wh1, bh1, Wh2, bh2, batch,
                                        pos, esrc, edst, out, N);
}

// round 7
// speedup vs baseline: 1.1083x; 1.1083x over previous
#include <cuda_runtime.h>
#include <math.h>

// Problem constants (fixed by the dataset)
#define NNODES   50000
#define FEAT     144        // C_RAD * SH_DIM
#define CRAD     16
#define SHD      9
#define NRBF     128
#define CUTOFF   5.0f
#define TBL      8192       // radial-table resolution
#define SLOTS    64         // edge-id bucket slots per node (overflow -> fallback)
#define OVF_CAP  8192

// ---------------- device scratch (no allocs allowed) ----------------
__device__ float g_table[(TBL + 1) * CRAD];     // rad(d) lookup (+ sentinel row)
__device__ float g_deg[(size_t)NNODES * FEAT];  // aggregated, PRE-SCALED by 1/sqrt(deg_avg)
__device__ int   g_cnt[NNODES];                 // per-dst edge count
__device__ int   g_eid[(size_t)NNODES * SLOTS]; // bucketed edge ids
__device__ int   g_ovf[OVF_CAP];                // overflow edge ids
__device__ int   g_ovfcnt;

#define INV_SQRT_DEG   0.25335570773f   // 1/sqrt(15.57930850982666)
#define INV_SQRT_NODES 0.23549661171f   // 1/sqrt(18.03065905448718)

__device__ __forceinline__ float silu_f(float x) {
    return x / (1.0f + expf(-x));
}

// f32x2 packed-FMA helpers (sm_103a)
__device__ __forceinline__ unsigned long long pk2(float lo, float hi) {
    unsigned long long r;
    asm("mov.b64 %0, {%1, %2};" : "=l"(r) : "f"(lo), "f"(hi));
    return r;
}
__device__ __forceinline__ void fma2(unsigned long long& d,
                                     unsigned long long a, unsigned long long b) {
    asm("fma.rn.f32x2 %0, %1, %2, %0;" : "+l"(d) : "l"(a), "l"(b));
}
__device__ __forceinline__ void unpk2(unsigned long long v, float& lo, float& hi) {
    asm("mov.b64 {%0, %1}, %2;" : "=f"(lo), "=f"(hi) : "l"(v));
}

// per-edge geometry: rad[16] (table interp) + sh[9]
__device__ __forceinline__ void edge_geom(float vx, float vy, float vz,
                                          float* rad, float* sh) {
    const float len = sqrtf(vx * vx + vy * vy + vz * vz);
    const float inv = 1.0f / fmaxf(len, 1e-12f);
    const float x = vx * inv, y = vy * inv, z = vz * inv;

    const float s3 = 1.7320508075688772f;
    const float s5 = 2.23606797749979f;
    const float s15 = 3.872983346207417f;
    sh[0] = 1.0f;
    sh[1] = s3 * x; sh[2] = s3 * y; sh[3] = s3 * z;
    sh[4] = s15 * x * z;
    sh[5] = s15 * x * y;
    sh[6] = s5 * (y * y - 0.5f * (x * x + z * z));
    sh[7] = s15 * y * z;
    sh[8] = 0.5f * s15 * (z * z - x * x);

    float u = len * ((float)TBL / CUTOFF);
    u = fminf(u, (float)TBL);
    int i0 = min((int)u, TBL - 1);
    float f = u - (float)i0;
    const float4* t0 = reinterpret_cast<const float4*>(g_table + (size_t)i0 * CRAD);
    const float4* t1 = reinterpret_cast<const float4*>(g_table + (size_t)(i0 + 1) * CRAD);
    #pragma unroll
    for (int q = 0; q < 4; q++) {
        float4 a = t0[q], b = t1[q];
        rad[4 * q + 0] = fmaf(f, b.x - a.x, a.x);
        rad[4 * q + 1] = fmaf(f, b.y - a.y, a.y);
        rad[4 * q + 2] = fmaf(f, b.z - a.z, a.z);
        rad[4 * q + 3] = fmaf(f, b.w - a.w, a.w);
    }
}

// ---------------- kernel A: zero counters + output ----------------
__global__ void zero_kernel(float* __restrict__ out, int G) {
    int i = blockIdx.x * blockDim.x + threadIdx.x;
    if (i < NNODES) g_cnt[i] = 0;
    if (i < G) out[i] = 0.0f;
    if (i == 0) g_ovfcnt = 0;
}

// ---------------- kernel B (fat): radial table + edge-id bucketing ----------------
__global__ void __launch_bounds__(256) fat_kernel(const float* __restrict__ W1, const float* __restrict__ b1,
                                                  const float* __restrict__ W2, const float* __restrict__ b2,
                                                  const float* __restrict__ W3,
                                                  const int* __restrict__ edst, int E) {
    if (blockIdx.x < TBL + 1) {
        __shared__ float s_rbf[NRBF];
        __shared__ float s_h1[64];
        __shared__ float s_h2[64];

        const int i = blockIdx.x;
        const int t = threadIdx.x;
        const float d = (float)i * (CUTOFF / (float)TBL);

        const double startd = 0.006737946999085467;          // exp(-5)
        const double width  = (2.0 / 128.0) * (1.0 - startd);
        const float  BETA   = (float)(1.0 / (width * width));

        if (t < NRBF) {
            const float mean = (float)(startd + (1.0 - startd) * ((double)t / 127.0));
            float cut = 0.0f;
            if (d < CUTOFF)
                cut = 0.5f * (cosf(d * (float)(3.14159265358979323846 / 5.0)) + 1.0f);
            const float ex = expf(-d);
            const float dd = ex - mean;
            s_rbf[t] = cut * expf(-BETA * dd * dd);
        }
        __syncthreads();

        if (t < 64) {
            float a = b1[t];
            #pragma unroll 8
            for (int k = 0; k < NRBF; k++) a = fmaf(s_rbf[k], W1[k * 64 + t], a);
            s_h1[t] = silu_f(a);
        }
        __syncthreads();
        if (t < 64) {
            float a = b2[t];
            #pragma unroll 8
            for (int k = 0; k < 64; k++) a = fmaf(s_h1[k], W2[k * 64 + t], a);
            s_h2[t] = silu_f(a);
        }
        __syncthreads();
        if (t < CRAD) {
            float a = 0.0f;
            #pragma unroll 8
            for (int k = 0; k < 64; k++) a = fmaf(s_h2[k], W3[k * CRAD + t], a);
            g_table[i * CRAD + t] = a;
        }
    } else {
        const int e = (blockIdx.x - (TBL + 1)) * 256 + threadIdx.x;
        if (e < E) {
            const int d = edst[e];
            const int pos = atomicAdd(&g_cnt[d], 1);
            if (pos < SLOTS) {
                g_eid[(size_t)d * SLOTS + pos] = e;
            } else {
                const int oi = atomicAdd(&g_ovfcnt, 1);
                if (oi < OVF_CAP) g_ovf[oi] = e;
            }
        }
    }
}

// ---------------- kernel C: warp-per-node gather ----------------
__global__ void __launch_bounds__(256) gather_kernel(const float* __restrict__ pos,
                                                     const int* __restrict__ esrc,
                                                     int N) {
    __shared__ float sE[8][32][29];   // [warp][edge][rad16|sh9|pad]

    const int w = threadIdx.x >> 5;           // warp in block
    const int lane = threadIdx.x & 31;
    const int n = blockIdx.x * 8 + w;         // node
    if (n >= N) return;

    const int deg = g_cnt[n];
    const int nslot = min(deg, SLOTS);

    const float pdx = pos[3 * (size_t)n + 0];
    const float pdy = pos[3 * (size_t)n + 1];
    const float pdz = pos[3 * (size_t)n + 2];

    const int c = lane >> 1;
    const int h = lane & 1;
    const int k0 = h ? 5 : 0;
    const int nk = h ? 4 : 5;

    float acc[5] = {0.f, 0.f, 0.f, 0.f, 0.f};

    for (int base = 0; base < nslot; base += 32) {
        const int cnt = min(nslot - base, 32);
        float rad[CRAD], sh[SHD];
        if (lane < cnt) {
            const int e = g_eid[(size_t)n * SLOTS + base + lane];
            const int s = esrc[e];
            const float vx = pos[3 * (size_t)s + 0] - pdx;
            const float vy = pos[3 * (size_t)s + 1] - pdy;
            const float vz = pos[3 * (size_t)s + 2] - pdz;
            edge_geom(vx, vy, vz, rad, sh);
            #pragma unroll
            for (int q = 0; q < CRAD; q++) sE[w][lane][q] = rad[q];
            #pragma unroll
            for (int q = 0; q < SHD; q++) sE[w][lane][CRAD + q] = sh[q];
        }
        __syncwarp();
        for (int e2 = 0; e2 < cnt; e2++) {
            const float r = sE[w][e2][c];
            #pragma unroll
            for (int m = 0; m < 5; m++) {
                if (m < nk) acc[m] = fmaf(r, sE[w][e2][CRAD + k0 + m], acc[m]);
            }
        }
        __syncwarp();
    }

    float* dst = g_deg + (size_t)n * FEAT + 9 * c + k0;
    #pragma unroll
    for (int m = 0; m < 5; m++) {
        if (m < nk) dst[m] = acc[m] * INV_SQRT_DEG;
    }
}

// ---------------- kernel D: node head (register-blocked GEMM) ----------------
// 288 threads = 18 tx (8 j each, j0 = 8*tx) x 16 ty (2 nodes: ty, ty+16).
// 16 outputs/thread = 8 independent f32x2 chains; k unrolled by 2 via LDS.128
// of dup-pair staging; w double-buffered in registers.
__global__ void __launch_bounds__(288) node_kernel(const float* __restrict__ atab,
                                                   const int* __restrict__ natom,
                                                   const float* __restrict__ Wh1,
                                                   const float* __restrict__ bh1,
                                                   const float* __restrict__ Wh2,
                                                   const float* __restrict__ bh2,
                                                   const int* __restrict__ batch,
                                                   const float* __restrict__ pos,
                                                   const int* __restrict__ esrc,
                                                   const int* __restrict__ edst,
                                                   float* __restrict__ out,
                                                   int N) {
    __shared__ unsigned long long sNF2[32][FEAT];   // 36,864 B: packed {v,v} per (node,k)
    __shared__ int s_atom[32];

    const int t = threadIdx.x;
    const int tx = t % 18;          // j0 = 8*tx
    const int ty = t / 18;          // 0..15
    const int nb = blockIdx.x * 32;

    if (t < 32) {
        const int gn = nb + t;
        s_atom[t] = (gn < N) ? natom[gn] : 0;
    }
    __syncthreads();

    // stage node features as dup-pairs, coalesced reads, conflict-free STS.64
    for (int idx = t; idx < 32 * (FEAT / 2); idx += 288) {
        const int n = idx / (FEAT / 2);
        const int kk = idx - n * (FEAT / 2);
        const int k = 2 * kk;
        const int gn = nb + n;
        float v0 = 0.0f, v1 = 0.0f;
        if (gn < N) {
            const float2 a = *reinterpret_cast<const float2*>(atab + (size_t)s_atom[n] * FEAT + k);
            const float2 g = *reinterpret_cast<const float2*>(g_deg + (size_t)gn * FEAT + k);
            v0 = a.x + g.x;
            v1 = a.y + g.y;
        }
        sNF2[n][k]     = pk2(v0, v0);
        sNF2[n][k + 1] = pk2(v1, v1);
    }
    __syncthreads();

    // overflow fixup (practically never taken for this graph)
    const int novf = g_ovfcnt;
    if (novf > 0) {
        for (int i = t; i < min(novf, OVF_CAP); i += 288) {
            const int e = g_ovf[i];
            const int d = edst[e];
            if (d >= nb && d < nb + 32 && d < N) {
                const int s = esrc[e];
                const float vx = pos[3 * (size_t)s + 0] - pos[3 * (size_t)d + 0];
                const float vy = pos[3 * (size_t)s + 1] - pos[3 * (size_t)d + 1];
                const float vz = pos[3 * (size_t)s + 2] - pos[3 * (size_t)d + 2];
                float rad[CRAD], sh[SHD];
                edge_geom(vx, vy, vz, rad, sh);
                float* row = reinterpret_cast<float*>(&sNF2[d - nb][0]);
                for (int j = 0; j < FEAT; j++) {
                    const float add = rad[j / SHD] * sh[j % SHD] * INV_SQRT_DEG;
                    atomicAdd(row + 2 * j + 0, add);
                    atomicAdd(row + 2 * j + 1, add);
                }
            }
        }
        __syncthreads();
    }

    const int j0 = 8 * tx;
    const float* Wrow = Wh1 + j0;

    unsigned long long acc[2][4];
    #pragma unroll
    for (int m = 0; m < 2; m++)
        #pragma unroll
        for (int q = 0; q < 4; q++) acc[m][q] = 0ULL;

    // prefetch w for k = 0,1
    float4 wa0 = __ldg(reinterpret_cast<const float4*>(Wrow + 0 * FEAT));
    float4 wa1 = __ldg(reinterpret_cast<const float4*>(Wrow + 0 * FEAT + 4));
    float4 wb0 = __ldg(reinterpret_cast<const float4*>(Wrow + 1 * FEAT));
    float4 wb1 = __ldg(reinterpret_cast<const float4*>(Wrow + 1 * FEAT + 4));

    #pragma unroll 2
    for (int k2 = 0; k2 < FEAT / 2; k2++) {
        const int k = 2 * k2;
        const float4 ca0 = wa0, ca1 = wa1, cb0 = wb0, cb1 = wb1;
        if (k2 + 1 < FEAT / 2) {
            wa0 = __ldg(reinterpret_cast<const float4*>(Wrow + (k + 2) * FEAT));
            wa1 = __ldg(reinterpret_cast<const float4*>(Wrow + (k + 2) * FEAT + 4));
            wb0 = __ldg(reinterpret_cast<const float4*>(Wrow + (k + 3) * FEAT));
            wb1 = __ldg(reinterpret_cast<const float4*>(Wrow + (k + 3) * FEAT + 4));
        }
        const ulonglong2 va = *reinterpret_cast<const ulonglong2*>(&sNF2[ty][k]);
        const ulonglong2 vb = *reinterpret_cast<const ulonglong2*>(&sNF2[ty + 16][k]);

        // k even
        fma2(acc[0][0], va.x, pk2(ca0.x, ca0.y));
        fma2(acc[0][1], va.x, pk2(ca0.z, ca0.w));
        fma2(acc[0][2], va.x, pk2(ca1.x, ca1.y));
        fma2(acc[0][3], va.x, pk2(ca1.z, ca1.w));
        fma2(acc[1][0], vb.x, pk2(ca0.x, ca0.y));
        fma2(acc[1][1], vb.x, pk2(ca0.z, ca0.w));
        fma2(acc[1][2], vb.x, pk2(ca1.x, ca1.y));
        fma2(acc[1][3], vb.x, pk2(ca1.z, ca1.w));
        // k odd
        fma2(acc[0][0], va.y, pk2(cb0.x, cb0.y));
        fma2(acc[0][1], va.y, pk2(cb0.z, cb0.w));
        fma2(acc[0][2], va.y, pk2(cb1.x, cb1.y));
        fma2(acc[0][3], va.y, pk2(cb1.z, cb1.w));
        fma2(acc[1][0], vb.y, pk2(cb0.x, cb0.y));
        fma2(acc[1][1], vb.y, pk2(cb0.z, cb0.w));
        fma2(acc[1][2], vb.y, pk2(cb1.x, cb1.y));
        fma2(acc[1][3], vb.y, pk2(cb1.z, cb1.w));
    }

    const float4 bA = *reinterpret_cast<const float4*>(bh1 + j0);
    const float4 bB = *reinterpret_cast<const float4*>(bh1 + j0 + 4);
    const float4 wA = *reinterpret_cast<const float4*>(Wh2 + j0);
    const float4 wB = *reinterpret_cast<const float4*>(Wh2 + j0 + 4);
    const float bias2 = bh2[0];

    #pragma unroll
    for (int m = 0; m < 2; m++) {
        const int gn = nb + ty + 16 * m;
        if (gn >= N) continue;
        float a0, a1, a2, a3, a4, a5, a6, a7;
        unpk2(acc[m][0], a0, a1);
        unpk2(acc[m][1], a2, a3);
        unpk2(acc[m][2], a4, a5);
        unpk2(acc[m][3], a6, a7);
        float p = silu_f(a0 + bA.x) * wA.x
                + silu_f(a1 + bA.y) * wA.y
                + silu_f(a2 + bA.z) * wA.z
                + silu_f(a3 + bA.w) * wA.w
                + silu_f(a4 + bB.x) * wB.x
                + silu_f(a5 + bB.y) * wB.y
                + silu_f(a6 + bB.z) * wB.z
                + silu_f(a7 + bB.w) * wB.w;
        if (tx == 0 && m == 0) p += bias2;
        if (tx == 0 && m == 1) p += bias2;
        atomicAdd(out + batch[gn], p * INV_SQRT_NODES);
    }
}

// ---------------- launcher ----------------
extern "C" void kernel_launch(void* const* d_in, const int* in_sizes, int n_in,
                              void* d_out, int out_size) {
    const float* pos  = (const float*)d_in[0];
    const float* atab = (const float*)d_in[1];
    const float* W1   = (const float*)d_in[2];
    const float* b1   = (const float*)d_in[3];
    const float* W2   = (const float*)d_in[4];
    const float* b2   = (const float*)d_in[5];
    const float* W3   = (const float*)d_in[6];
    const float* Wh1  = (const float*)d_in[7];
    const float* bh1  = (const float*)d_in[8];
    const float* Wh2  = (const float*)d_in[9];
    const float* bh2  = (const float*)d_in[10];
    const int* natom  = (const int*)d_in[11];
    const int* esrc   = (const int*)d_in[12];
    const int* edst   = (const int*)d_in[13];
    const int* batch  = (const int*)d_in[14];
    float* out = (float*)d_out;

    const int N = in_sizes[11];
    const int E = in_sizes[12];
    const int G = out_size;

    // 1: zero counters + output
    zero_kernel<<<(NNODES + 255) / 256, 256>>>(out, G);

    // 2: radial table + edge bucketing
    const int scatter_blocks = (E + 255) / 256;
    fat_kernel<<<(TBL + 1) + scatter_blocks, 256>>>(W1, b1, W2, b2, W3, edst, E);

    // 3: warp-per-node gather
    gather_kernel<<<(N + 7) / 8, 256>>>(pos, esrc, N);

    // 4: node GEMM + head + graph reduction — profiled launch
    node_kernel<<<(N + 31) / 32, 288>>>(atab, natom, Wh1, bh1, Wh2, bh2, batch,
                                        pos, esrc, edst, out, N);
}

// round 8
// speedup vs baseline: 1.8215x; 1.6436x over previous
#include <cuda_runtime.h>
#include <math.h>

// Problem constants (fixed by the dataset)
#define NNODES   50000
#define FEAT     144        // C_RAD * SH_DIM
#define CRAD     16
#define SHD      9
#define NRBF     128
#define CUTOFF   5.0f
#define TBL      8192       // radial-table resolution
#define SLOTS    64         // edge-id bucket slots per node (overflow -> fallback)
#define OVF_CAP  8192

// node_kernel tiling
#define NTILE    128        // nodes per block
#define VSTRIDE  145        // smem feature-row stride (odd -> conflict-free)
#define NWARP    12         // warps per block; each owns 12 j's

// ---------------- device scratch (no allocs allowed) ----------------
__device__ float g_table[(TBL + 1) * CRAD];     // rad(d) lookup (+ sentinel row)
__device__ float g_deg[(size_t)NNODES * FEAT];  // aggregated, PRE-SCALED by 1/sqrt(deg_avg)
__device__ int   g_cnt[NNODES];                 // per-dst edge count
__device__ int   g_eid[(size_t)NNODES * SLOTS]; // bucketed edge ids
__device__ int   g_ovf[OVF_CAP];                // overflow edge ids
__device__ int   g_ovfcnt;

#define INV_SQRT_DEG   0.25335570773f   // 1/sqrt(15.57930850982666)
#define INV_SQRT_NODES 0.23549661171f   // 1/sqrt(18.03065905448718)

__device__ __forceinline__ float silu_f(float x) {
    return x / (1.0f + expf(-x));
}

// f32x2 packed-FMA helpers (sm_103a)
__device__ __forceinline__ unsigned long long pk2(float lo, float hi) {
    unsigned long long r;
    asm("mov.b64 %0, {%1, %2};" : "=l"(r) : "f"(lo), "f"(hi));
    return r;
}
__device__ __forceinline__ void fma2(unsigned long long& d,
                                     unsigned long long a, unsigned long long b) {
    asm("fma.rn.f32x2 %0, %1, %2, %0;" : "+l"(d) : "l"(a), "l"(b));
}
__device__ __forceinline__ void unpk2(unsigned long long v, float& lo, float& hi) {
    asm("mov.b64 {%0, %1}, %2;" : "=f"(lo), "=f"(hi) : "l"(v));
}

// per-edge geometry: rad[16] (table interp) + sh[9]
__device__ __forceinline__ void edge_geom(float vx, float vy, float vz,
                                          float* rad, float* sh) {
    const float len = sqrtf(vx * vx + vy * vy + vz * vz);
    const float inv = 1.0f / fmaxf(len, 1e-12f);
    const float x = vx * inv, y = vy * inv, z = vz * inv;

    const float s3 = 1.7320508075688772f;
    const float s5 = 2.23606797749979f;
    const float s15 = 3.872983346207417f;
    sh[0] = 1.0f;
    sh[1] = s3 * x; sh[2] = s3 * y; sh[3] = s3 * z;
    sh[4] = s15 * x * z;
    sh[5] = s15 * x * y;
    sh[6] = s5 * (y * y - 0.5f * (x * x + z * z));
    sh[7] = s15 * y * z;
    sh[8] = 0.5f * s15 * (z * z - x * x);

    float u = len * ((float)TBL / CUTOFF);
    u = fminf(u, (float)TBL);
    int i0 = min((int)u, TBL - 1);
    float f = u - (float)i0;
    const float4* t0 = reinterpret_cast<const float4*>(g_table + (size_t)i0 * CRAD);
    const float4* t1 = reinterpret_cast<const float4*>(g_table + (size_t)(i0 + 1) * CRAD);
    #pragma unroll
    for (int q = 0; q < 4; q++) {
        float4 a = t0[q], b = t1[q];
        rad[4 * q + 0] = fmaf(f, b.x - a.x, a.x);
        rad[4 * q + 1] = fmaf(f, b.y - a.y, a.y);
        rad[4 * q + 2] = fmaf(f, b.z - a.z, a.z);
        rad[4 * q + 3] = fmaf(f, b.w - a.w, a.w);
    }
}

// ---------------- kernel A: zero counters + output ----------------
__global__ void zero_kernel(float* __restrict__ out, int G) {
    int i = blockIdx.x * blockDim.x + threadIdx.x;
    if (i < NNODES) g_cnt[i] = 0;
    if (i < G) out[i] = 0.0f;
    if (i == 0) g_ovfcnt = 0;
}

// ---------------- kernel B (fat): radial table + edge-id bucketing ----------------
__global__ void __launch_bounds__(256) fat_kernel(const float* __restrict__ W1, const float* __restrict__ b1,
                                                  const float* __restrict__ W2, const float* __restrict__ b2,
                                                  const float* __restrict__ W3,
                                                  const int* __restrict__ edst, int E) {
    if (blockIdx.x < TBL + 1) {
        __shared__ float s_rbf[NRBF];
        __shared__ float s_h1[64];
        __shared__ float s_h2[64];

        const int i = blockIdx.x;
        const int t = threadIdx.x;
        const float d = (float)i * (CUTOFF / (float)TBL);

        const double startd = 0.006737946999085467;          // exp(-5)
        const double width  = (2.0 / 128.0) * (1.0 - startd);
        const float  BETA   = (float)(1.0 / (width * width));

        if (t < NRBF) {
            const float mean = (float)(startd + (1.0 - startd) * ((double)t / 127.0));
            float cut = 0.0f;
            if (d < CUTOFF)
                cut = 0.5f * (cosf(d * (float)(3.14159265358979323846 / 5.0)) + 1.0f);
            const float ex = expf(-d);
            const float dd = ex - mean;
            s_rbf[t] = cut * expf(-BETA * dd * dd);
        }
        __syncthreads();

        if (t < 64) {
            float a = b1[t];
            #pragma unroll 8
            for (int k = 0; k < NRBF; k++) a = fmaf(s_rbf[k], W1[k * 64 + t], a);
            s_h1[t] = silu_f(a);
        }
        __syncthreads();
        if (t < 64) {
            float a = b2[t];
            #pragma unroll 8
            for (int k = 0; k < 64; k++) a = fmaf(s_h1[k], W2[k * 64 + t], a);
            s_h2[t] = silu_f(a);
        }
        __syncthreads();
        if (t < CRAD) {
            float a = 0.0f;
            #pragma unroll 8
            for (int k = 0; k < 64; k++) a = fmaf(s_h2[k], W3[k * CRAD + t], a);
            g_table[i * CRAD + t] = a;
        }
    } else {
        const int e = (blockIdx.x - (TBL + 1)) * 256 + threadIdx.x;
        if (e < E) {
            const int d = edst[e];
            const int pos = atomicAdd(&g_cnt[d], 1);
            if (pos < SLOTS) {
                g_eid[(size_t)d * SLOTS + pos] = e;
            } else {
                const int oi = atomicAdd(&g_ovfcnt, 1);
                if (oi < OVF_CAP) g_ovf[oi] = e;
            }
        }
    }
}

// ---------------- kernel C: warp-per-node gather ----------------
__global__ void __launch_bounds__(256) gather_kernel(const float* __restrict__ pos,
                                                     const int* __restrict__ esrc,
                                                     int N) {
    __shared__ float sE[8][32][29];   // [warp][edge][rad16|sh9|pad]

    const int w = threadIdx.x >> 5;           // warp in block
    const int lane = threadIdx.x & 31;
    const int n = blockIdx.x * 8 + w;         // node
    if (n >= N) return;

    const int deg = g_cnt[n];
    const int nslot = min(deg, SLOTS);

    const float pdx = pos[3 * (size_t)n + 0];
    const float pdy = pos[3 * (size_t)n + 1];
    const float pdz = pos[3 * (size_t)n + 2];

    const int c = lane >> 1;
    const int h = lane & 1;
    const int k0 = h ? 5 : 0;
    const int nk = h ? 4 : 5;

    float acc[5] = {0.f, 0.f, 0.f, 0.f, 0.f};

    for (int base = 0; base < nslot; base += 32) {
        const int cnt = min(nslot - base, 32);
        float rad[CRAD], sh[SHD];
        if (lane < cnt) {
            const int e = g_eid[(size_t)n * SLOTS + base + lane];
            const int s = esrc[e];
            const float vx = pos[3 * (size_t)s + 0] - pdx;
            const float vy = pos[3 * (size_t)s + 1] - pdy;
            const float vz = pos[3 * (size_t)s + 2] - pdz;
            edge_geom(vx, vy, vz, rad, sh);
            #pragma unroll
            for (int q = 0; q < CRAD; q++) sE[w][lane][q] = rad[q];
            #pragma unroll
            for (int q = 0; q < SHD; q++) sE[w][lane][CRAD + q] = sh[q];
        }
        __syncwarp();
        for (int e2 = 0; e2 < cnt; e2++) {
            const float r = sE[w][e2][c];
            #pragma unroll
            for (int m = 0; m < 5; m++) {
                if (m < nk) acc[m] = fmaf(r, sE[w][e2][CRAD + k0 + m], acc[m]);
            }
        }
        __syncwarp();
    }

    float* dst = g_deg + (size_t)n * FEAT + 9 * c + k0;
    #pragma unroll
    for (int m = 0; m < 5; m++) {
        if (m < nk) dst[m] = acc[m] * INV_SQRT_DEG;
    }
}

// ---------------- kernel D: node head GEMM, all-smem mainloop ----------------
// 384 threads = 12 warps. Warp w owns j in [12w, 12w+12). Lane ln owns nodes
// ln + 32q (q<4) of the 128-node tile. Weight reads: warp-uniform LDS.128
// broadcasts (1 wavefront). Feature reads: LDS.32, stride-145 rows (no conflicts).
// Zero LDG in the mainloop.
__global__ void __launch_bounds__(NWARP * 32) node_kernel(const float* __restrict__ atab,
                                                          const int* __restrict__ natom,
                                                          const float* __restrict__ Wh1,
                                                          const float* __restrict__ bh1,
                                                          const float* __restrict__ Wh2,
                                                          const float* __restrict__ bh2,
                                                          const int* __restrict__ batch,
                                                          const float* __restrict__ pos,
                                                          const int* __restrict__ esrc,
                                                          const int* __restrict__ edst,
                                                          float* __restrict__ out,
                                                          int N) {
    extern __shared__ float smem[];
    float* sW = smem;                      // [FEAT][FEAT]   = 82,944 B
    float* sV = smem + FEAT * FEAT;        // [NTILE][VSTRIDE] = 74,240 B
    __shared__ int s_batch[NTILE];

    const int t = threadIdx.x;
    const int w = t >> 5;                  // warp id: j0 = 12*w
    const int ln = t & 31;                 // lane = node within group of 32
    const int nb = blockIdx.x * NTILE;

    // stage Wh1 (coalesced float4 copy)
    for (int idx = t; idx < (FEAT * FEAT) / 4; idx += NWARP * 32) {
        reinterpret_cast<float4*>(sW)[idx] =
            __ldg(reinterpret_cast<const float4*>(Wh1) + idx);
    }

    // stage node features: atab[natom] + g_deg (pre-scaled)
    for (int idx = t; idx < NTILE * (FEAT / 2); idx += NWARP * 32) {
        const int n = idx / (FEAT / 2);
        const int kk = idx - n * (FEAT / 2);
        const int k = 2 * kk;
        const int gn = nb + n;
        float v0 = 0.0f, v1 = 0.0f;
        if (gn < N) {
            const float2 a = *reinterpret_cast<const float2*>(atab + (size_t)natom[gn] * FEAT + k);
            const float2 g = *reinterpret_cast<const float2*>(g_deg + (size_t)gn * FEAT + k);
            v0 = a.x + g.x;
            v1 = a.y + g.y;
        }
        sV[n * VSTRIDE + k]     = v0;
        sV[n * VSTRIDE + k + 1] = v1;
    }
    if (t < NTILE) {
        const int gn = nb + t;
        s_batch[t] = (gn < N) ? batch[gn] : 0;
    }
    __syncthreads();

    // overflow fixup (practically never taken for this graph)
    const int novf = g_ovfcnt;
    if (novf > 0) {
        for (int i = t; i < min(novf, OVF_CAP); i += NWARP * 32) {
            const int e = g_ovf[i];
            const int d = edst[e];
            if (d >= nb && d < nb + NTILE && d < N) {
                const int s = esrc[e];
                const float vx = pos[3 * (size_t)s + 0] - pos[3 * (size_t)d + 0];
                const float vy = pos[3 * (size_t)s + 1] - pos[3 * (size_t)d + 1];
                const float vz = pos[3 * (size_t)s + 2] - pos[3 * (size_t)d + 2];
                float rad[CRAD], sh[SHD];
                edge_geom(vx, vy, vz, rad, sh);
                for (int j = 0; j < FEAT; j++) {
                    atomicAdd(&sV[(d - nb) * VSTRIDE + j],
                              rad[j / SHD] * sh[j % SHD] * INV_SQRT_DEG);
                }
            }
        }
        __syncthreads();
    }

    const int j0 = 12 * w;                 // 48B-aligned (16B ok)

    unsigned long long acc[4][6];          // [node-group q][j-pair]
    #pragma unroll
    for (int q = 0; q < 4; q++)
        #pragma unroll
        for (int p = 0; p < 6; p++) acc[q][p] = 0ULL;

    const float* sWj = sW + j0;
    #pragma unroll 4
    for (int k = 0; k < FEAT; k++) {
        // warp-uniform broadcasts: 12 weights = 6 packed pairs
        const ulonglong2 wpA = *reinterpret_cast<const ulonglong2*>(sWj + k * FEAT);
        const ulonglong2 wpB = *reinterpret_cast<const ulonglong2*>(sWj + k * FEAT + 4);
        const ulonglong2 wpC = *reinterpret_cast<const ulonglong2*>(sWj + k * FEAT + 8);
        #pragma unroll
        for (int q = 0; q < 4; q++) {
            const float v = sV[(ln + 32 * q) * VSTRIDE + k];
            const unsigned long long vv = pk2(v, v);
            fma2(acc[q][0], vv, wpA.x);
            fma2(acc[q][1], vv, wpA.y);
            fma2(acc[q][2], vv, wpB.x);
            fma2(acc[q][3], vv, wpB.y);
            fma2(acc[q][4], vv, wpC.x);
            fma2(acc[q][5], vv, wpC.y);
        }
    }

    // epilogue: silu + dot with Wh2 slice, partial-energy atomics
    float bj[12], w2[12];
    #pragma unroll
    for (int p = 0; p < 12; p++) {
        bj[p] = bh1[j0 + p];
        w2[p] = Wh2[j0 + p];
    }
    const float bias2 = bh2[0];

    #pragma unroll
    for (int q = 0; q < 4; q++) {
        const int n = ln + 32 * q;
        const int gn = nb + n;
        if (gn >= N) continue;
        float p = 0.0f;
        #pragma unroll
        for (int pp = 0; pp < 6; pp++) {
            float a0, a1;
            unpk2(acc[q][pp], a0, a1);
            p += silu_f(a0 + bj[2 * pp])     * w2[2 * pp];
            p += silu_f(a1 + bj[2 * pp + 1]) * w2[2 * pp + 1];
        }
        if (w == 0) p += bias2;
        atomicAdd(out + s_batch[n], p * INV_SQRT_NODES);
    }
}

#define NODE_SMEM ((FEAT * FEAT + NTILE * VSTRIDE) * 4)

// ---------------- launcher ----------------
extern "C" void kernel_launch(void* const* d_in, const int* in_sizes, int n_in,
                              void* d_out, int out_size) {
    const float* pos  = (const float*)d_in[0];
    const float* atab = (const float*)d_in[1];
    const float* W1   = (const float*)d_in[2];
    const float* b1   = (const float*)d_in[3];
    const float* W2   = (const float*)d_in[4];
    const float* b2   = (const float*)d_in[5];
    const float* W3   = (const float*)d_in[6];
    const float* Wh1  = (const float*)d_in[7];
    const float* bh1  = (const float*)d_in[8];
    const float* Wh2  = (const float*)d_in[9];
    const float* bh2  = (const float*)d_in[10];
    const int* natom  = (const int*)d_in[11];
    const int* esrc   = (const int*)d_in[12];
    const int* edst   = (const int*)d_in[13];
    const int* batch  = (const int*)d_in[14];
    float* out = (float*)d_out;

    const int N = in_sizes[11];
    const int E = in_sizes[12];
    const int G = out_size;

    static bool attr_done = false;
    if (!attr_done) {
        cudaFuncSetAttribute(node_kernel,
                             cudaFuncAttributeMaxDynamicSharedMemorySize, NODE_SMEM);
        attr_done = true;
    }

    // 1: zero counters + output
    zero_kernel<<<(NNODES + 255) / 256, 256>>>(out, G);

    // 2: radial table + edge bucketing
    const int scatter_blocks = (E + 255) / 256;
    fat_kernel<<<(TBL + 1) + scatter_blocks, 256>>>(W1, b1, W2, b2, W3, edst, E);

    // 3: warp-per-node gather
    gather_kernel<<<(N + 7) / 8, 256>>>(pos, esrc, N);

    // 4: node GEMM + head + graph reduction — profiled launch
    node_kernel<<<(N + NTILE - 1) / NTILE, NWARP * 32, NODE_SMEM>>>(
        atab, natom, Wh1, bh1, Wh2, bh2, batch, pos, esrc, edst, out, N);
}